// round 11
// baseline (speedup 1.0000x reference)
#include <cuda_runtime.h>
#include <stdint.h>
#include <math.h>

#define NB 8192
#define ND 128
#define NS 16
#define NBLK 32
#define TM 128
#define TN 128
#define TK 16
#define PAD 4                 // row stride 132 floats = 528 B = 33*16 -> float4-aligned
#define MARGIN 0.8f
#define EPSF 1e-6f
#define MAXP (NB + NS*128)
#define MAXT 4096
#define PAIR_GRID 148

// ---------------- device scratch (no allocations allowed) ----------------
__device__ int                 g_order[MAXP];   // bucket slot -> original row (pads = 0)
__device__ int                 g_labp [MAXP];
__device__ int                 g_perm [MAXP];
__device__ int                 g_bh   [NBLK * NS];
__device__ int                 g_bbase[NBLK * NS];
__device__ int                 g_cnt_s[NS];
__device__ int                 g_poff [NS];
__device__ int                 g_tiles[MAXT];   // packed (s | ti<<8 | tj<<16)
__device__ int                 g_ntiles;
__device__ unsigned long long  g_pos[NB];       // (ordf(key)<<32) | (~j) ; argmax
__device__ unsigned long long  g_neg[NB];       // (ordf(key)<<32) | ( j) ; argmin
__device__ float               g_sum;
__device__ int                 g_cnt;
__device__ unsigned int        g_done1;         // count_kernel last-block
__device__ unsigned int        g_done2;         // triplet_kernel last-block

__device__ __forceinline__ unsigned int ordf(float f) {
    unsigned int u = __float_as_uint(f);
    return (u & 0x80000000u) ? ~u : (u | 0x80000000u);
}

// ---------------- k1: histogram + sentinels; LAST BLOCK does all planning ----------------
__global__ __launch_bounds__(256) void count_kernel(const int* __restrict__ sbj) {
    __shared__ int h[NS];
    __shared__ bool amlast;
    const int t = threadIdx.x, b = blockIdx.x, lane = t & 31;
    if (t < NS) h[t] = 0;
    __syncthreads();

    const int i = b * 256 + t;
    {   // warp-aggregated histogram
        int s = sbj[i];
        unsigned peers = __match_any_sync(0xFFFFFFFFu, s);
        if ((__ffs(peers) - 1) == lane) atomicAdd(&h[s], __popc(peers));
    }
    g_pos[i] = 0ull;
    g_neg[i] = ~0ull;
    for (int p = i; p < MAXP; p += NBLK * 256) g_order[p] = 0;  // pads -> valid row 0
    if (b == 0 && t == 0) { g_sum = 0.f; g_cnt = 0; g_done2 = 0u; }
    __syncthreads();
    if (t < NS) g_bh[b * NS + t] = h[t];

    // last arriving block performs planning
    __threadfence();
    if (t == 0) {
        unsigned d = atomicAdd(&g_done1, 1u) + 1u;
        amlast = (d == (unsigned)NBLK);
        if (amlast) g_done1 = 0u;   // reset for next replay
    }
    __syncthreads();
    if (!amlast) return;

    __shared__ int cshr[NS], toff_s[NS];
    if (t < NS) {
        int c = 0;
        for (int bb = 0; bb < NBLK; bb++) c += g_bh[bb * NS + t];
        g_cnt_s[t] = c;
        cshr[t] = c;
    }
    __syncthreads();
    if (t == 0) {
        int acc = 0, tacc = 0;
        for (int s = 0; s < NS; s++) {
            int m = (cshr[s] + 127) >> 7;
            g_poff[s] = acc;  acc  += m << 7;
            toff_s[s] = tacc; tacc += m * m;
        }
        g_ntiles = tacc;
    }
    __syncthreads();
    if (t < NS) {
        int acc = g_poff[t];
        for (int bb = 0; bb < NBLK; bb++) {      // per-block slot bases
            g_bbase[bb * NS + t] = acc;
            acc += g_bh[bb * NS + t];
        }
        int m = (cshr[t] + 127) >> 7;            // tile worklist
        int base = toff_s[t];
        for (int ti = 0; ti < m; ti++)
            for (int tj = 0; tj < m; tj++)
                g_tiles[base++] = t | (ti << 8) | (tj << 16);
    }
}

// ---------------- k2: slot assignment (warp-aggregated, order-unstable = OK) ----------------
__global__ __launch_bounds__(256) void order_kernel(const int* __restrict__ labels,
                                                    const int* __restrict__ sbj) {
    __shared__ int h[NS];
    const int t = threadIdx.x, b = blockIdx.x, lane = t & 31;
    if (t < NS) h[t] = 0;
    __syncthreads();

    const int i = b * 256 + t;
    const int s = sbj[i];
    unsigned peers = __match_any_sync(0xFFFFFFFFu, s);
    int leader = __ffs(peers) - 1;
    int rb = 0;
    if (lane == leader) rb = atomicAdd(&h[s], __popc(peers));
    rb = __shfl_sync(0xFFFFFFFFu, rb, leader);
    const int slot = g_bbase[b * NS + s] + rb + __popc(peers & ((1u << lane) - 1u));
    g_order[slot] = i;
    g_labp [slot] = labels[i];
    g_perm [slot] = i;
}

// ---------------- k3: persistent fused Gram + masked argmax/argmin ----------------
// key = (s_j - 2*dot): per-row constant s_i cancels in arg-selection; column
// norms computed from the B smem tile. Single-buffer smem, register prefetch.
__global__ __launch_bounds__(256, 1) void pair_kernel(const float* __restrict__ emb) {
    __shared__ __align__(16) float As[TK][TM + PAD];
    __shared__ __align__(16) float Bs[TK][TN + PAD];
    __shared__ int   rlab[TM], rperm[TM], clab[TN], cperm[TN];
    __shared__ float cns[256];

    const int tid = threadIdx.x;
    const int tx  = tid & 15;
    const int ty  = tid >> 4;
    const int m1  = tid >> 2;     // load rows m1, m1+64
    const int q   = tid & 3;      // float4 index within chunk
    const int ccol = tid & 127;   // column-norm ownership
    const int kh   = (tid >> 7) * 8;
    const int ntiles = g_ntiles;

    for (int t = blockIdx.x; t < ntiles; t += gridDim.x) {
        const int desc = g_tiles[t];
        const int s  = desc & 255;
        const int ti = (desc >> 8) & 255;
        const int tj = (desc >> 16) & 255;
        const int n    = g_cnt_s[s];
        const int base = g_poff[s];
        const int rbase = base + ti * TM;
        const int cbase = base + tj * TN;

        __syncthreads();   // prev tile's epilogue done before smem overwrite
        if (tid < TM) {
            rlab[tid]  = g_labp[rbase + tid];
            rperm[tid] = g_perm[rbase + tid];
            clab[tid]  = g_labp[cbase + tid];
            cperm[tid] = g_perm[cbase + tid];
        }
        const float4* pa0 = (const float4*)(emb + (size_t)g_order[rbase + m1]      * ND) + q;
        const float4* pa1 = (const float4*)(emb + (size_t)g_order[rbase + m1 + 64] * ND) + q;
        const float4* pb0 = (const float4*)(emb + (size_t)g_order[cbase + m1]      * ND) + q;
        const float4* pb1 = (const float4*)(emb + (size_t)g_order[cbase + m1 + 64] * ND) + q;

        float acc[8][8];
#pragma unroll
        for (int a = 0; a < 8; a++)
#pragma unroll
            for (int b = 0; b < 8; b++) acc[a][b] = 0.f;
        float cn = 0.f;

        // chunk 0 into smem
        float4 va0 = pa0[0], va1 = pa1[0], vb0 = pb0[0], vb1 = pb1[0];
        As[q*4+0][m1] = va0.x; As[q*4+1][m1] = va0.y; As[q*4+2][m1] = va0.z; As[q*4+3][m1] = va0.w;
        As[q*4+0][m1+64] = va1.x; As[q*4+1][m1+64] = va1.y; As[q*4+2][m1+64] = va1.z; As[q*4+3][m1+64] = va1.w;
        Bs[q*4+0][m1] = vb0.x; Bs[q*4+1][m1] = vb0.y; Bs[q*4+2][m1] = vb0.z; Bs[q*4+3][m1] = vb0.w;
        Bs[q*4+0][m1+64] = vb1.x; Bs[q*4+1][m1+64] = vb1.y; Bs[q*4+2][m1+64] = vb1.z; Bs[q*4+3][m1+64] = vb1.w;
        __syncthreads();

#pragma unroll
        for (int ch = 0; ch < 8; ch++) {
            if (ch < 7) {   // prefetch next chunk into registers (overlaps compute)
                const int idx = 4 * (ch + 1);
                va0 = pa0[idx]; va1 = pa1[idx]; vb0 = pb0[idx]; vb1 = pb1[idx];
            }
#pragma unroll
            for (int k = 0; k < TK; k++) {
                float4 a0 = *(const float4*)&As[k][ty * 4];
                float4 a1 = *(const float4*)&As[k][64 + ty * 4];
                float4 b0 = *(const float4*)&Bs[k][tx * 4];
                float4 b1 = *(const float4*)&Bs[k][64 + tx * 4];
                float ra[8] = {a0.x,a0.y,a0.z,a0.w,a1.x,a1.y,a1.z,a1.w};
                float rb[8] = {b0.x,b0.y,b0.z,b0.w,b1.x,b1.y,b1.z,b1.w};
#pragma unroll
                for (int a = 0; a < 8; a++)
#pragma unroll
                    for (int b = 0; b < 8; b++) acc[a][b] += ra[a] * rb[b];
            }
#pragma unroll
            for (int k = 0; k < 8; k++) {        // column squared-norm piece
                float v = Bs[kh + k][ccol];
                cn += v * v;
            }
            if (ch < 7) {
                __syncthreads();
                As[q*4+0][m1] = va0.x; As[q*4+1][m1] = va0.y; As[q*4+2][m1] = va0.z; As[q*4+3][m1] = va0.w;
                As[q*4+0][m1+64] = va1.x; As[q*4+1][m1+64] = va1.y; As[q*4+2][m1+64] = va1.z; As[q*4+3][m1+64] = va1.w;
                Bs[q*4+0][m1] = vb0.x; Bs[q*4+1][m1] = vb0.y; Bs[q*4+2][m1] = vb0.z; Bs[q*4+3][m1] = vb0.w;
                Bs[q*4+0][m1+64] = vb1.x; Bs[q*4+1][m1+64] = vb1.y; Bs[q*4+2][m1+64] = vb1.z; Bs[q*4+3][m1+64] = vb1.w;
                __syncthreads();
            }
        }
        cns[tid] = cn;
        __syncthreads();

        // epilogue: per-thread masked best keys, shuffle-reduce across tx, 1 atomic/row
#pragma unroll
        for (int a = 0; a < 8; a++) {
            const int  rrow   = (a < 4) ? (ty * 4 + a) : (64 + ty * 4 + a - 4);
            const int  il     = ti * TM + rrow;
            const bool rvalid = (il < n);
            const int  ll = rlab [rrow];
            const int  io = rperm[rrow];
            unsigned long long kp = 0ull, kn = ~0ull;
#pragma unroll
            for (int b = 0; b < 8; b++) {
                const int bcol = (b < 4) ? (tx * 4 + b) : (64 + tx * 4 + b - 4);
                const int jl   = tj * TN + bcol;
                if (rvalid && jl < n) {
                    const float sj  = cns[bcol] + cns[bcol + 128];
                    const float d2v = sj - 2.f * acc[a][b];   // s_i dropped (row-constant)
                    const int   jo  = cperm[bcol];
                    if (clab[bcol] == ll) {
                        if (jo != io) {
                            unsigned long long key =
                                ((unsigned long long)ordf(d2v) << 32) |
                                (unsigned long long)(0xFFFFFFFFu - (unsigned)jo);
                            if (key > kp) kp = key;   // ties -> smaller original j
                        }
                    } else {
                        unsigned long long key =
                            ((unsigned long long)ordf(d2v) << 32) |
                            (unsigned long long)(unsigned)jo;
                        if (key < kn) kn = key;       // ties -> smaller original j
                    }
                }
            }
#pragma unroll
            for (int o = 1; o < 16; o <<= 1) {
                unsigned long long op = __shfl_xor_sync(0xFFFFFFFFu, kp, o);
                unsigned long long on = __shfl_xor_sync(0xFFFFFFFFu, kn, o);
                if (op > kp) kp = op;
                if (on < kn) kn = on;
            }
            if (tx == 0 && rvalid) {
                if (kp != 0ull)  atomicMax(&g_pos[io], kp);
                if (kn != ~0ull) atomicMin(&g_neg[io], kn);
            }
        }
    }
}

// ---------------- k4: triplet distances + loss + in-kernel finalize ----------------
__global__ __launch_bounds__(256) void triplet_kernel(const float* __restrict__ emb,
                                                      float* __restrict__ out) {
    const int w    = (blockIdx.x * 256 + threadIdx.x) >> 5;
    const int lane = threadIdx.x & 31;

    const unsigned long long kp = g_pos[w];
    const unsigned long long kn = g_neg[w];
    if ((kp != 0ull) && (kn != ~0ull)) {
        const int p = (int)(0xFFFFFFFFu - (unsigned)kp);
        const int n = (int)(unsigned)kn;

        const float4 a4 = ((const float4*)(emb + (size_t)w * ND))[lane];
        const float4 p4 = ((const float4*)(emb + (size_t)p * ND))[lane];
        const float4 n4 = ((const float4*)(emb + (size_t)n * ND))[lane];

        float dx, s1, s2;
        dx = a4.x - p4.x + EPSF; s1  = dx * dx;   // torch pairwise_distance eps quirk
        dx = a4.y - p4.y + EPSF; s1 += dx * dx;
        dx = a4.z - p4.z + EPSF; s1 += dx * dx;
        dx = a4.w - p4.w + EPSF; s1 += dx * dx;
        dx = a4.x - n4.x + EPSF; s2  = dx * dx;
        dx = a4.y - n4.y + EPSF; s2 += dx * dx;
        dx = a4.z - n4.z + EPSF; s2 += dx * dx;
        dx = a4.w - n4.w + EPSF; s2 += dx * dx;

#pragma unroll
        for (int o = 16; o > 0; o >>= 1) {
            s1 += __shfl_down_sync(0xFFFFFFFFu, s1, o);
            s2 += __shfl_down_sync(0xFFFFFFFFu, s2, o);
        }
        if (lane == 0) {
            float per = fmaxf(sqrtf(s1) - sqrtf(s2) + MARGIN, 0.f);
            atomicAdd(&g_sum, per);
            atomicAdd(&g_cnt, 1);
        }
    }

    __syncthreads();
    if (threadIdx.x == 0) {
        __threadfence();
        unsigned done = atomicAdd(&g_done2, 1u) + 1u;
        if (done == gridDim.x) {
            float sm = atomicAdd(&g_sum, 0.f);
            int   c  = atomicAdd(&g_cnt, 0);
            out[0] = (c > 0) ? sm / (float)c : 0.f;
            g_done2 = 0u;  // reset for next replay (count also resets; idempotent)
        }
    }
}

// ---------------- launch ----------------
extern "C" void kernel_launch(void* const* d_in, const int* in_sizes, int n_in,
                              void* d_out, int out_size) {
    const float* emb    = (const float*)d_in[0];
    const int*   labels = (const int*)d_in[1];
    const int*   sbj    = (const int*)d_in[2];
    float*       out    = (float*)d_out;

    count_kernel  <<<NBLK, 256>>>(sbj);
    order_kernel  <<<NBLK, 256>>>(labels, sbj);
    pair_kernel   <<<PAIR_GRID, 256>>>(emb);
    triplet_kernel<<<NB / 8, 256>>>(emb, out);
}

// round 12
// speedup vs baseline: 1.5402x; 1.5402x over previous
#include <cuda_runtime.h>
#include <stdint.h>
#include <math.h>

#define NB 8192
#define ND 128
#define NS 16
#define NBLK 32
#define TM 128
#define TN 128
#define TK 16
#define MARGIN 0.8f
#define EPSF 1e-6f
#define MAXP (NB + NS*128)
#define MAXT 4096
#define PAIR_GRID 384

// ---------------- device scratch (no allocations allowed) ----------------
__device__ float               g_embp[(size_t)MAXP * ND];  // bucketed embeddings (pads: bss zeros)
__device__ float               g_sqp [MAXP];
__device__ int                 g_labp[MAXP];
__device__ int                 g_perm[MAXP];
__device__ int                 g_bh   [NBLK * NS];
__device__ int                 g_bbase[NBLK * NS];
__device__ int                 g_cnt_s[NS];
__device__ int                 g_poff [NS];
__device__ int                 g_tiles[MAXT];   // packed (s | ti<<8 | tj<<16)
__device__ int                 g_ntiles;
__device__ unsigned long long  g_pos[NB];       // (ordf(d2)<<32) | (~j) ; argmax
__device__ unsigned long long  g_neg[NB];       // (ordf(d2)<<32) | ( j) ; argmin
__device__ float               g_sum;
__device__ int                 g_cnt;
__device__ unsigned int        g_done1, g_done2;

__device__ __forceinline__ unsigned int ordf(float f) {
    unsigned int u = __float_as_uint(f);
    return (u & 0x80000000u) ? ~u : (u | 0x80000000u);
}

// ---------------- k1: histogram + sentinels; LAST BLOCK plans ----------------
__global__ __launch_bounds__(256) void count_plan_kernel(const int* __restrict__ sbj) {
    __shared__ int h[NS];
    __shared__ bool amlast;
    const int t = threadIdx.x, b = blockIdx.x, lane = t & 31;
    if (t < NS) h[t] = 0;
    __syncthreads();

    const int i = b * 256 + t;
    {
        int s = sbj[i];
        unsigned peers = __match_any_sync(0xFFFFFFFFu, s);
        if ((__ffs(peers) - 1) == lane) atomicAdd(&h[s], __popc(peers));
    }
    g_pos[i] = 0ull;
    g_neg[i] = ~0ull;
    if (b == 0 && t == 0) { g_sum = 0.f; g_cnt = 0; g_done2 = 0u; }
    __syncthreads();
    if (t < NS) g_bh[b * NS + t] = h[t];

    __threadfence();
    if (t == 0) {
        unsigned d = atomicAdd(&g_done1, 1u) + 1u;
        amlast = (d == (unsigned)NBLK);
        if (amlast) g_done1 = 0u;   // reset for next graph replay
    }
    __syncthreads();
    if (!amlast) return;

    __shared__ int cshr[NS], toff_s[NS];
    if (t < NS) {
        int c = 0;
        for (int bb = 0; bb < NBLK; bb++) c += g_bh[bb * NS + t];
        g_cnt_s[t] = c;
        cshr[t] = c;
    }
    __syncthreads();
    if (t == 0) {
        int acc = 0, tacc = 0;
        for (int s = 0; s < NS; s++) {
            int m = (cshr[s] + 127) >> 7;
            g_poff[s] = acc;  acc  += m << 7;
            toff_s[s] = tacc; tacc += m * m;
        }
        g_ntiles = tacc;
    }
    __syncthreads();
    if (t < NS) {
        int acc = g_poff[t];
        for (int bb = 0; bb < NBLK; bb++) {
            g_bbase[bb * NS + t] = acc;
            acc += g_bh[bb * NS + t];
        }
        int m = (cshr[t] + 127) >> 7;
        int base = toff_s[t];
        for (int ti = 0; ti < m; ti++)
            for (int tj = 0; tj < m; tj++)
                g_tiles[base++] = t | (ti << 8) | (tj << 16);
    }
}

// ---------------- k2: rank (smem) + coalesced copy + norms, one kernel ----------------
// Block b owns original rows [b*256, b*256+256). Ranks via smem atomics (no
// global-atomic serialization); bucket-internal order is arbitrary = OK.
__global__ __launch_bounds__(1024) void scatter_kernel(const float* __restrict__ emb,
                                                       const int*   __restrict__ labels,
                                                       const int*   __restrict__ sbj) {
    __shared__ int h[NS];
    __shared__ int sslot[256];
    const int t = threadIdx.x, b = blockIdx.x;
    if (t < NS) h[t] = 0;
    __syncthreads();

    if (t < 256) {
        const int i = b * 256 + t;
        const int s = sbj[i];
        const int r = atomicAdd(&h[s], 1);
        const int slot = g_bbase[b * NS + s] + r;
        sslot[t] = slot;
        g_labp[slot] = labels[i];
        g_perm[slot] = i;
    }
    __syncthreads();

    // 32 warps copy 256 rows (8 rows per warp), coalesced both sides
    const int w = t >> 5, lane = t & 31;
#pragma unroll
    for (int r = 0; r < 8; r++) {
        const int lr   = w * 8 + r;
        const int slot = sslot[lr];
        const float4 v = ((const float4*)(emb + (size_t)(b * 256 + lr) * ND))[lane];
        ((float4*)(g_embp + (size_t)slot * ND))[lane] = v;
        float s = v.x * v.x + v.y * v.y + v.z * v.z + v.w * v.w;
#pragma unroll
        for (int o = 16; o > 0; o >>= 1) s += __shfl_down_sync(0xFFFFFFFFu, s, o);
        if (lane == 0) g_sqp[slot] = s;
    }
}

// ---------------- k3: persistent fused Gram + masked argmax/argmin ----------------
// R4 mainloop structure, but conflict-free LDS.128 split fragments.
__global__ __launch_bounds__(256) void pair_kernel() {
    __shared__ __align__(16) float As[TK][TM + 4];
    __shared__ __align__(16) float Bs[TK][TN + 4];
    __shared__ int   rlab[TM], rperm[TM];
    __shared__ int   clab[TN], cperm[TN];
    __shared__ float rsq[TM], csq[TN];

    const int tid = threadIdx.x;
    const int tx  = tid & 15;
    const int ty  = tid >> 4;
    const int ntiles = g_ntiles;

    for (int t = blockIdx.x; t < ntiles; t += gridDim.x) {
        const int desc = g_tiles[t];
        const int s  = desc & 255;
        const int ti = (desc >> 8) & 255;
        const int tj = (desc >> 16) & 255;
        const int n    = g_cnt_s[s];
        const int base = g_poff[s];
        const int rbase = base + ti * TM;
        const int cbase = base + tj * TN;

        __syncthreads();   // prev tile epilogue done before smem overwrite
        if (tid < TM) {
            rlab[tid]  = g_labp[rbase + tid];
            rperm[tid] = g_perm[rbase + tid];
            rsq[tid]   = g_sqp [rbase + tid];
            clab[tid]  = g_labp[cbase + tid];
            cperm[tid] = g_perm[cbase + tid];
            csq[tid]   = g_sqp [cbase + tid];
        }

        float acc[8][8];
#pragma unroll
        for (int a = 0; a < 8; a++)
#pragma unroll
            for (int b = 0; b < 8; b++) acc[a][b] = 0.f;

        for (int kk = 0; kk < ND; kk += TK) {
            __syncthreads();
#pragma unroll
            for (int r = 0; r < 2; r++) {
                int l = tid + r * 256;          // 0..511
                int m = l >> 2;                 // 0..127
                int q = l & 3;
                float4 v = *reinterpret_cast<const float4*>(g_embp + (size_t)(rbase + m) * ND + kk + q * 4);
                As[q * 4 + 0][m] = v.x; As[q * 4 + 1][m] = v.y;
                As[q * 4 + 2][m] = v.z; As[q * 4 + 3][m] = v.w;
                float4 w = *reinterpret_cast<const float4*>(g_embp + (size_t)(cbase + m) * ND + kk + q * 4);
                Bs[q * 4 + 0][m] = w.x; Bs[q * 4 + 1][m] = w.y;
                Bs[q * 4 + 2][m] = w.z; Bs[q * 4 + 3][m] = w.w;
            }
            __syncthreads();
#pragma unroll
            for (int k = 0; k < TK; k++) {
                // split fragments: rows {ty*4..+3, 64+ty*4..+3}, cols likewise.
                // LDS.128, 8-lane phases read 128 contiguous bytes -> conflict-free.
                float4 a0 = *(const float4*)&As[k][ty * 4];
                float4 a1 = *(const float4*)&As[k][64 + ty * 4];
                float4 b0 = *(const float4*)&Bs[k][tx * 4];
                float4 b1 = *(const float4*)&Bs[k][64 + tx * 4];
                float ra[8] = {a0.x,a0.y,a0.z,a0.w,a1.x,a1.y,a1.z,a1.w};
                float rb[8] = {b0.x,b0.y,b0.z,b0.w,b1.x,b1.y,b1.z,b1.w};
#pragma unroll
                for (int a = 0; a < 8; a++)
#pragma unroll
                    for (int b = 0; b < 8; b++) acc[a][b] += ra[a] * rb[b];
            }
        }

        // epilogue: masked best keys, shuffle-reduce across 16 tx lanes, 1 atomic/row
#pragma unroll
        for (int a = 0; a < 8; a++) {
            const int  rrow   = (a < 4) ? (ty * 4 + a) : (64 + ty * 4 + (a - 4));
            const int  il     = ti * TM + rrow;
            const bool rvalid = (il < n);
            const int   ll = rlab [rrow];
            const int   io = rperm[rrow];
            const float si = rsq  [rrow];
            unsigned long long kp = 0ull, kn = ~0ull;
#pragma unroll
            for (int b = 0; b < 8; b++) {
                const int bcol = (b < 4) ? (tx * 4 + b) : (64 + tx * 4 + (b - 4));
                const int jl   = tj * TN + bcol;
                if (rvalid && jl < n) {
                    const float d2v = si + csq[bcol] - 2.f * acc[a][b];
                    const int   jo  = cperm[bcol];
                    if (clab[bcol] == ll) {
                        if (jo != io) {
                            unsigned long long key =
                                ((unsigned long long)ordf(d2v) << 32) |
                                (unsigned long long)(0xFFFFFFFFu - (unsigned)jo);
                            if (key > kp) kp = key;   // ties -> smaller original j
                        }
                    } else {
                        unsigned long long key =
                            ((unsigned long long)ordf(d2v) << 32) |
                            (unsigned long long)(unsigned)jo;
                        if (key < kn) kn = key;       // ties -> smaller original j
                    }
                }
            }
#pragma unroll
            for (int o = 1; o < 16; o <<= 1) {
                unsigned long long op = __shfl_xor_sync(0xFFFFFFFFu, kp, o);
                unsigned long long on = __shfl_xor_sync(0xFFFFFFFFu, kn, o);
                if (op > kp) kp = op;
                if (on < kn) kn = on;
            }
            if (tx == 0 && rvalid) {
                if (kp != 0ull)  atomicMax(&g_pos[io], kp);
                if (kn != ~0ull) atomicMin(&g_neg[io], kn);
            }
        }
    }
}

// ---------------- k4: triplet distances + loss + in-kernel finalize ----------------
__global__ __launch_bounds__(256) void triplet_kernel(const float* __restrict__ emb,
                                                      float* __restrict__ out) {
    const int wbase = (blockIdx.x * 8 + (threadIdx.x >> 5)) * 2;  // 2 rows per warp
    const int lane  = threadIdx.x & 31;

#pragma unroll
    for (int rr = 0; rr < 2; rr++) {
        const int w = wbase + rr;
        const unsigned long long kp = g_pos[w];
        const unsigned long long kn = g_neg[w];
        if ((kp != 0ull) && (kn != ~0ull)) {
            const int p = (int)(0xFFFFFFFFu - (unsigned)kp);
            const int n = (int)(unsigned)kn;

            const float4 a4 = ((const float4*)(emb + (size_t)w * ND))[lane];
            const float4 p4 = ((const float4*)(emb + (size_t)p * ND))[lane];
            const float4 n4 = ((const float4*)(emb + (size_t)n * ND))[lane];

            float dx, s1, s2;
            dx = a4.x - p4.x + EPSF; s1  = dx * dx;   // torch pairwise_distance eps quirk
            dx = a4.y - p4.y + EPSF; s1 += dx * dx;
            dx = a4.z - p4.z + EPSF; s1 += dx * dx;
            dx = a4.w - p4.w + EPSF; s1 += dx * dx;
            dx = a4.x - n4.x + EPSF; s2  = dx * dx;
            dx = a4.y - n4.y + EPSF; s2 += dx * dx;
            dx = a4.z - n4.z + EPSF; s2 += dx * dx;
            dx = a4.w - n4.w + EPSF; s2 += dx * dx;

#pragma unroll
            for (int o = 16; o > 0; o >>= 1) {
                s1 += __shfl_down_sync(0xFFFFFFFFu, s1, o);
                s2 += __shfl_down_sync(0xFFFFFFFFu, s2, o);
            }
            if (lane == 0) {
                float per = fmaxf(sqrtf(s1) - sqrtf(s2) + MARGIN, 0.f);
                atomicAdd(&g_sum, per);
                atomicAdd(&g_cnt, 1);
            }
        }
    }

    __syncthreads();
    if (threadIdx.x == 0) {
        __threadfence();
        unsigned done = atomicAdd(&g_done2, 1u) + 1u;
        if (done == gridDim.x) {
            float sm = atomicAdd(&g_sum, 0.f);
            int   c  = atomicAdd(&g_cnt, 0);
            out[0] = (c > 0) ? sm / (float)c : 0.f;
            g_done2 = 0u;   // reset for next replay
        }
    }
}

// ---------------- launch ----------------
extern "C" void kernel_launch(void* const* d_in, const int* in_sizes, int n_in,
                              void* d_out, int out_size) {
    const float* emb    = (const float*)d_in[0];
    const int*   labels = (const int*)d_in[1];
    const int*   sbj    = (const int*)d_in[2];
    float*       out    = (float*)d_out;

    count_plan_kernel<<<NBLK, 256>>>(sbj);
    scatter_kernel   <<<NBLK, 1024>>>(emb, labels, sbj);
    pair_kernel      <<<PAIR_GRID, 256>>>();
    triplet_kernel   <<<NB / 16, 256>>>(emb, out);
}

// round 13
// speedup vs baseline: 2.0412x; 1.3253x over previous
#include <cuda_runtime.h>
#include <stdint.h>
#include <math.h>

#define NB 8192
#define ND 128
#define NS 16
#define NBLK 32
#define TM 128
#define TN 64            // half-tile columns
#define TK 16
#define MARGIN 0.8f
#define EPSF 1e-6f
#define MAXP (NB + NS*128)
#define MAXT 8192
#define PAIR_GRID 296

// ---------------- device scratch (no allocations allowed) ----------------
__device__ float               g_embp[(size_t)MAXP * ND];  // bucketed embeddings (pads stay 0)
__device__ float               g_sqp [MAXP];
__device__ int                 g_labp[MAXP];
__device__ int                 g_perm[MAXP];
__device__ int                 g_bh   [NBLK * NS];
__device__ int                 g_bbase[NBLK * NS];
__device__ int                 g_cnt_s[NS];
__device__ int                 g_poff [NS];
__device__ int                 g_tiles[MAXT];   // packed (s | ti<<8 | tj<<16 | h<<24)
__device__ int                 g_ntiles;
__device__ unsigned long long  g_pos[NB];       // (ordf(d2)<<32) | (~j) ; argmax
__device__ unsigned long long  g_neg[NB];       // (ordf(d2)<<32) | ( j) ; argmin
__device__ float               g_sum;
__device__ int                 g_cnt;
__device__ unsigned int        g_done1, g_done2, g_done3;
__device__ unsigned int        g_flag;          // 0 at every launch entry (reset by done3)

__device__ __forceinline__ unsigned int ordf(float f) {
    unsigned int u = __float_as_uint(f);
    return (u & 0x80000000u) ? ~u : (u | 0x80000000u);
}

// ---------------- k1: histogram + plan (last block) + spin + scatter, fused ----------------
// 32 co-resident blocks. g_flag lifecycle: 0 at entry (bss / reset by previous
// run's done3), 1 after planning, 0 again once all blocks finish scatter.
__global__ __launch_bounds__(1024) void prep_kernel(const float* __restrict__ emb,
                                                    const int*   __restrict__ labels,
                                                    const int*   __restrict__ sbj) {
    __shared__ int h[NS];
    __shared__ int sslot[256];
    __shared__ bool amlast;
    const int t = threadIdx.x, b = blockIdx.x, lane = t & 31;

    if (t < NS) h[t] = 0;
    if (b == 0 && t == 32) { g_sum = 0.f; g_cnt = 0; g_done2 = 0u; }
    __syncthreads();

    // phase A: histogram + sentinels (first 256 threads; block owns 256 rows)
    if (t < 256) {
        const int i = b * 256 + t;
        int s = sbj[i];
        unsigned peers = __match_any_sync(0xFFFFFFFFu, s);
        if ((__ffs(peers) - 1) == lane) atomicAdd(&h[s], __popc(peers));
        g_pos[i] = 0ull;
        g_neg[i] = ~0ull;
    }
    __syncthreads();
    if (t < NS) g_bh[b * NS + t] = h[t];

    __threadfence();
    if (t == 0) {
        unsigned d = atomicAdd(&g_done1, 1u) + 1u;
        amlast = (d == (unsigned)NBLK);
        if (amlast) g_done1 = 0u;   // reset for next replay
    }
    __syncthreads();

    if (amlast) {
        // phase B: planning (block-uniform branch, syncthreads legal)
        __shared__ int cshr[NS], toff_s[NS];
        if (t < NS) {
            int c = 0;
            for (int bb = 0; bb < NBLK; bb++) c += g_bh[bb * NS + t];
            g_cnt_s[t] = c;
            cshr[t] = c;
        }
        __syncthreads();
        if (t == 0) {
            int acc = 0, tacc = 0;
            for (int s = 0; s < NS; s++) {
                int m = (cshr[s] + 127) >> 7;
                g_poff[s] = acc;  acc  += m << 7;
                toff_s[s] = tacc; tacc += m * (m + 1);   // sym tiles * 2 halves
            }
            g_ntiles = tacc;
        }
        __syncthreads();
        if (t < NS) {
            int acc = g_poff[t];
            for (int bb = 0; bb < NBLK; bb++) {
                g_bbase[bb * NS + t] = acc;
                acc += g_bh[bb * NS + t];
            }
            int m = (cshr[t] + 127) >> 7;
            int base = toff_s[t];
            for (int ti = 0; ti < m; ti++)
                for (int tj = ti; tj < m; tj++)
                    for (int hh = 0; hh < 2; hh++)
                        g_tiles[base++] = t | (ti << 8) | (tj << 16) | (hh << 24);
        }
        __syncthreads();
        __threadfence();
        if (t == 0) atomicExch(&g_flag, 1u);   // release
    } else {
        if (t == 0) { while (atomicAdd(&g_flag, 0u) == 0u) { } }   // acquire spin
    }
    __syncthreads();
    __threadfence();

    // phase C: scatter (rank via smem atomics + coalesced copy + norms)
    if (t < NS) h[t] = 0;
    __syncthreads();
    if (t < 256) {
        const int i = b * 256 + t;
        const int s = sbj[i];
        const int r = atomicAdd(&h[s], 1);
        const int slot = g_bbase[b * NS + s] + r;
        sslot[t] = slot;
        g_labp[slot] = labels[i];
        g_perm[slot] = i;
    }
    __syncthreads();

    const int w = t >> 5;
#pragma unroll
    for (int r = 0; r < 8; r++) {
        const int lr   = w * 8 + r;
        const int slot = sslot[lr];
        const float4 v = ((const float4*)(emb + (size_t)(b * 256 + lr) * ND))[lane];
        ((float4*)(g_embp + (size_t)slot * ND))[lane] = v;
        float s = v.x * v.x + v.y * v.y + v.z * v.z + v.w * v.w;
#pragma unroll
        for (int o = 16; o > 0; o >>= 1) s += __shfl_down_sync(0xFFFFFFFFu, s, o);
        if (lane == 0) g_sqp[slot] = s;
    }

    // last finisher resets flag (keeps lifecycle invariant across replays)
    __syncthreads();
    __threadfence();
    if (t == 0) {
        unsigned d = atomicAdd(&g_done3, 1u) + 1u;
        if (d == (unsigned)NBLK) { g_done3 = 0u; g_flag = 0u; }
    }
}

// ---------------- k2: persistent fused Gram over SYMMETRIC half-tiles ----------------
// Each 128x64 half-tile updates row bests (128 rows over 64 cols) and, for
// off-diagonal tiles, column bests (64 cols over 128 rows) via d2 symmetry.
__global__ __launch_bounds__(256) void pair_kernel() {
    __shared__ __align__(16) float As[TK][TM + 4];
    __shared__ __align__(16) float Bs[TK][TN + 4];
    __shared__ int   rlab[TM], rperm[TM];
    __shared__ float rsq[TM];
    __shared__ int   clab[TN], cperm[TN];
    __shared__ float csq[TN];
    __shared__ unsigned long long colP[8][TN], colN[8][TN];

    const int tid = threadIdx.x;
    const int tx  = tid & 15;    // 16 col-threads x 4 cols
    const int ty  = tid >> 4;    // 16 row-threads x 8 rows (split 4+4)
    const int ntiles = g_ntiles;

    for (int t = blockIdx.x; t < ntiles; t += gridDim.x) {
        const int desc = g_tiles[t];
        const int s  = desc & 255;
        const int ti = (desc >> 8) & 255;
        const int tj = (desc >> 16) & 255;
        const int hh = (desc >> 24) & 1;
        const int n    = g_cnt_s[s];
        const int base = g_poff[s];
        const int rbase = base + ti * 128;
        const int cbase = base + tj * 128 + hh * 64;
        const int jl0   = tj * 128 + hh * 64;      // subject-local index of col 0

        __syncthreads();   // prev tile fully done before smem overwrite
        if (tid < TM) {
            rlab[tid]  = g_labp[rbase + tid];
            rperm[tid] = g_perm[rbase + tid];
            rsq[tid]   = g_sqp [rbase + tid];
        }
        if (tid < TN) {
            clab[tid]  = g_labp[cbase + tid];
            cperm[tid] = g_perm[cbase + tid];
            csq[tid]   = g_sqp [cbase + tid];
        }

        float acc[8][4];
#pragma unroll
        for (int a = 0; a < 8; a++)
#pragma unroll
            for (int b = 0; b < 4; b++) acc[a][b] = 0.f;

        for (int kk = 0; kk < ND; kk += TK) {
            __syncthreads();
#pragma unroll
            for (int r = 0; r < 2; r++) {          // A: 128 rows
                int l = tid + r * 256;
                int m = l >> 2;
                int q = l & 3;
                float4 v = *reinterpret_cast<const float4*>(g_embp + (size_t)(rbase + m) * ND + kk + q * 4);
                As[q * 4 + 0][m] = v.x; As[q * 4 + 1][m] = v.y;
                As[q * 4 + 2][m] = v.z; As[q * 4 + 3][m] = v.w;
            }
            {                                       // B: 64 rows
                int m = tid >> 2;
                int q = tid & 3;
                float4 w = *reinterpret_cast<const float4*>(g_embp + (size_t)(cbase + m) * ND + kk + q * 4);
                Bs[q * 4 + 0][m] = w.x; Bs[q * 4 + 1][m] = w.y;
                Bs[q * 4 + 2][m] = w.z; Bs[q * 4 + 3][m] = w.w;
            }
            __syncthreads();
#pragma unroll
            for (int k = 0; k < TK; k++) {
                float4 a0 = *(const float4*)&As[k][ty * 4];
                float4 a1 = *(const float4*)&As[k][64 + ty * 4];
                float4 b0 = *(const float4*)&Bs[k][tx * 4];
                float ra[8] = {a0.x,a0.y,a0.z,a0.w,a1.x,a1.y,a1.z,a1.w};
                float rb[4] = {b0.x,b0.y,b0.z,b0.w};
#pragma unroll
                for (int a = 0; a < 8; a++)
#pragma unroll
                    for (int b = 0; b < 4; b++) acc[a][b] += ra[a] * rb[b];
            }
        }

        // ---- row epilogue: best over this tile's 64 cols, per row ----
#pragma unroll
        for (int a = 0; a < 8; a++) {
            const int  rrow   = (a < 4) ? (ty * 4 + a) : (64 + ty * 4 + (a - 4));
            const int  il     = ti * 128 + rrow;
            const bool rvalid = (il < n);
            const int   ll = rlab [rrow];
            const int   io = rperm[rrow];
            const float si = rsq  [rrow];
            unsigned long long kp = 0ull, kn = ~0ull;
#pragma unroll
            for (int b = 0; b < 4; b++) {
                const int bcol = tx * 4 + b;
                if (rvalid && (jl0 + bcol) < n) {
                    const float d2v = si + csq[bcol] - 2.f * acc[a][b];
                    const int   jo  = cperm[bcol];
                    if (clab[bcol] == ll) {
                        if (jo != io) {
                            unsigned long long key =
                                ((unsigned long long)ordf(d2v) << 32) |
                                (unsigned long long)(0xFFFFFFFFu - (unsigned)jo);
                            if (key > kp) kp = key;
                        }
                    } else {
                        unsigned long long key =
                            ((unsigned long long)ordf(d2v) << 32) |
                            (unsigned long long)(unsigned)jo;
                        if (key < kn) kn = key;
                    }
                }
            }
#pragma unroll
            for (int o = 1; o < 16; o <<= 1) {      // reduce across 16 tx lanes
                unsigned long long op = __shfl_xor_sync(0xFFFFFFFFu, kp, o);
                unsigned long long on = __shfl_xor_sync(0xFFFFFFFFu, kn, o);
                if (op > kp) kp = op;
                if (on < kn) kn = on;
            }
            if (tx == 0 && rvalid) {
                if (kp != 0ull)  atomicMax(&g_pos[io], kp);
                if (kn != ~0ull) atomicMin(&g_neg[io], kn);
            }
        }

        // ---- column epilogue (symmetry): best over this tile's 128 rows, per col ----
        if (ti != tj) {
            __syncthreads();   // all threads past mainloop before colP/colN writes
#pragma unroll
            for (int b = 0; b < 4; b++) {
                const int bcol = tx * 4 + b;
                unsigned long long cp = 0ull, cn_ = ~0ull;
                if ((jl0 + bcol) < n) {
                    const int   llj = clab[bcol];
                    const int   jo  = cperm[bcol];
                    const float sj  = csq [bcol];
#pragma unroll
                    for (int a = 0; a < 8; a++) {
                        const int rrow = (a < 4) ? (ty * 4 + a) : (64 + ty * 4 + (a - 4));
                        if (ti * 128 + rrow < n) {
                            const float d2v = rsq[rrow] + sj - 2.f * acc[a][b];
                            const int   io  = rperm[rrow];
                            if (rlab[rrow] == llj) {    // pos candidate for col j, partner i
                                if (io != jo) {
                                    unsigned long long key =
                                        ((unsigned long long)ordf(d2v) << 32) |
                                        (unsigned long long)(0xFFFFFFFFu - (unsigned)io);
                                    if (key > cp) cp = key;
                                }
                            } else {
                                unsigned long long key =
                                    ((unsigned long long)ordf(d2v) << 32) |
                                    (unsigned long long)(unsigned)io;
                                if (key < cn_) cn_ = key;
                            }
                        }
                    }
                }
                // in-warp reduce across ty parity (lane xor 16)
                unsigned long long op = __shfl_xor_sync(0xFFFFFFFFu, cp,  16);
                unsigned long long on = __shfl_xor_sync(0xFFFFFFFFu, cn_, 16);
                if (op > cp)  cp  = op;
                if (on < cn_) cn_ = on;
                if ((ty & 1) == 0) {
                    colP[ty >> 1][bcol] = cp;
                    colN[ty >> 1][bcol] = cn_;
                }
            }
            __syncthreads();
            if (tid < TN) {
                unsigned long long k = colP[0][tid];
#pragma unroll
                for (int w = 1; w < 8; w++) { unsigned long long v = colP[w][tid]; if (v > k) k = v; }
                if (k != 0ull) atomicMax(&g_pos[cperm[tid]], k);
            } else if (tid < 2 * TN) {
                const int c = tid - TN;
                unsigned long long k = colN[0][c];
#pragma unroll
                for (int w = 1; w < 8; w++) { unsigned long long v = colN[w][c]; if (v < k) k = v; }
                if (k != ~0ull) atomicMin(&g_neg[cperm[c]], k);
            }
        }
    }
}

// ---------------- k3: triplet distances + hierarchical loss reduce + finalize ----------------
__global__ __launch_bounds__(256) void triplet_kernel(const float* __restrict__ emb,
                                                      float* __restrict__ out) {
    __shared__ float bsum;
    __shared__ int   bcnt;
    if (threadIdx.x == 0) { bsum = 0.f; bcnt = 0; }
    __syncthreads();

    const int wbase = (blockIdx.x * 8 + (threadIdx.x >> 5)) * 2;  // 2 rows per warp
    const int lane  = threadIdx.x & 31;

    float lsum = 0.f;
    int   lcnt = 0;
#pragma unroll
    for (int rr = 0; rr < 2; rr++) {
        const int w = wbase + rr;
        const unsigned long long kp = g_pos[w];
        const unsigned long long kn = g_neg[w];
        if ((kp != 0ull) && (kn != ~0ull)) {
            const int p = (int)(0xFFFFFFFFu - (unsigned)kp);
            const int n = (int)(unsigned)kn;

            const float4 a4 = ((const float4*)(emb + (size_t)w * ND))[lane];
            const float4 p4 = ((const float4*)(emb + (size_t)p * ND))[lane];
            const float4 n4 = ((const float4*)(emb + (size_t)n * ND))[lane];

            float dx, s1, s2;
            dx = a4.x - p4.x + EPSF; s1  = dx * dx;   // torch pairwise_distance eps quirk
            dx = a4.y - p4.y + EPSF; s1 += dx * dx;
            dx = a4.z - p4.z + EPSF; s1 += dx * dx;
            dx = a4.w - p4.w + EPSF; s1 += dx * dx;
            dx = a4.x - n4.x + EPSF; s2  = dx * dx;
            dx = a4.y - n4.y + EPSF; s2 += dx * dx;
            dx = a4.z - n4.z + EPSF; s2 += dx * dx;
            dx = a4.w - n4.w + EPSF; s2 += dx * dx;

#pragma unroll
            for (int o = 16; o > 0; o >>= 1) {
                s1 += __shfl_down_sync(0xFFFFFFFFu, s1, o);
                s2 += __shfl_down_sync(0xFFFFFFFFu, s2, o);
            }
            if (lane == 0) {
                lsum += fmaxf(sqrtf(s1) - sqrtf(s2) + MARGIN, 0.f);
                lcnt += 1;
            }
        }
    }
    if (lane == 0 && lcnt > 0) {           // 8 smem atomics per block
        atomicAdd(&bsum, lsum);
        atomicAdd(&bcnt, lcnt);
    }
    __syncthreads();
    if (threadIdx.x == 0) {
        if (bcnt > 0) {                    // 2 global atomics per block
            atomicAdd(&g_sum, bsum);
            atomicAdd(&g_cnt, bcnt);
        }
        __threadfence();
        unsigned done = atomicAdd(&g_done2, 1u) + 1u;
        if (done == gridDim.x) {
            float sm = atomicAdd(&g_sum, 0.f);
            int   c  = atomicAdd(&g_cnt, 0);
            out[0] = (c > 0) ? sm / (float)c : 0.f;
            g_done2 = 0u;   // reset for next replay
        }
    }
}

// ---------------- launch ----------------
extern "C" void kernel_launch(void* const* d_in, const int* in_sizes, int n_in,
                              void* d_out, int out_size) {
    const float* emb    = (const float*)d_in[0];
    const int*   labels = (const int*)d_in[1];
    const int*   sbj    = (const int*)d_in[2];
    float*       out    = (float*)d_out;

    prep_kernel   <<<NBLK, 1024>>>(emb, labels, sbj);
    pair_kernel   <<<PAIR_GRID, 256>>>();
    triplet_kernel<<<NB / 16, 256>>>(emb, out);
}

// round 14
// speedup vs baseline: 2.1085x; 1.0330x over previous
#include <cuda_runtime.h>
#include <stdint.h>
#include <math.h>

#define NB 8192
#define ND 128
#define NS 16
#define NBLK 32
#define TT 64            // symmetric tile dim (64x64)
#define TK 16
#define MARGIN 0.8f
#define EPSF 1e-6f
#define MAXP (NB + NS*128)
#define MAXT 8704
#define PAIR_GRID 296

// ---------------- device scratch (no allocations allowed) ----------------
__device__ float               g_sq  [NB];      // row squared norms, ORIGINAL order
__device__ int                 g_order[MAXP];   // bucket slot -> original row (pads = 0)
__device__ int                 g_bh   [NBLK * NS];
__device__ int                 g_bbase[NBLK * NS];
__device__ int                 g_cnt_s[NS];
__device__ int                 g_poff [NS];
__device__ int                 g_tiles[MAXT];   // packed (s | ti<<8 | tj<<16), tj>=ti, 64-grain
__device__ int                 g_ntiles;
__device__ unsigned long long  g_pos[NB];       // (ordf(d2)<<32) | (~j) ; argmax
__device__ unsigned long long  g_neg[NB];       // (ordf(d2)<<32) | ( j) ; argmin
__device__ float               g_sum;
__device__ int                 g_cnt;
__device__ unsigned int        g_done1, g_done2, g_done3;
__device__ unsigned int        g_flag;          // 0 at entry; 1 after plan; reset by done3

__device__ __forceinline__ unsigned int ordf(float f) {
    unsigned int u = __float_as_uint(f);
    return (u & 0x80000000u) ? ~u : (u | 0x80000000u);
}

// ---------------- k1: norms + histogram + plan(last block) + slot assign ----------------
__global__ __launch_bounds__(1024) void prep_kernel(const float* __restrict__ emb,
                                                    const int*   __restrict__ sbj) {
    __shared__ int h[NS];
    __shared__ bool amlast;
    const int t = threadIdx.x, b = blockIdx.x, lane = t & 31;

    if (t < NS) h[t] = 0;
    if (b == 0 && t == 32) { g_sum = 0.f; g_cnt = 0; g_done2 = 0u; }
    __syncthreads();

    // phase A: histogram + sentinels (first 256 threads own block's 256 rows)
    if (t < 256) {
        const int i = b * 256 + t;
        int s = sbj[i];
        unsigned peers = __match_any_sync(0xFFFFFFFFu, s);
        if ((__ffs(peers) - 1) == lane) atomicAdd(&h[s], __popc(peers));
        g_pos[i] = 0ull;
        g_neg[i] = ~0ull;
    }
    // phase A': row norms in original order (32 warps x 8 rows, coalesced)
    {
        const int w = t >> 5;
#pragma unroll
        for (int r = 0; r < 8; r++) {
            const int row = b * 256 + w * 8 + r;
            const float4 v = ((const float4*)(emb + (size_t)row * ND))[lane];
            float s = v.x * v.x + v.y * v.y + v.z * v.z + v.w * v.w;
#pragma unroll
            for (int o = 16; o > 0; o >>= 1) s += __shfl_down_sync(0xFFFFFFFFu, s, o);
            if (lane == 0) g_sq[row] = s;
        }
    }
    __syncthreads();
    if (t < NS) g_bh[b * NS + t] = h[t];

    __threadfence();
    if (t == 0) {
        unsigned d = atomicAdd(&g_done1, 1u) + 1u;
        amlast = (d == (unsigned)NBLK);
        if (amlast) g_done1 = 0u;   // reset for next replay
    }
    __syncthreads();

    if (amlast) {
        // phase B: planning (block-uniform branch)
        __shared__ int cshr[NS], toff_s[NS];
        if (t < NS) {
            int c = 0;
            for (int bb = 0; bb < NBLK; bb++) c += g_bh[bb * NS + t];
            g_cnt_s[t] = c;
            cshr[t] = c;
        }
        __syncthreads();
        if (t == 0) {
            int acc = 0, tacc = 0;
            for (int s = 0; s < NS; s++) {
                int m = (cshr[s] + (TT - 1)) / TT;
                g_poff[s] = acc;  acc  += m * TT;
                toff_s[s] = tacc; tacc += m * (m + 1) / 2;
            }
            g_ntiles = tacc;
        }
        __syncthreads();
        if (t < NS) {
            int acc = g_poff[t];
            for (int bb = 0; bb < NBLK; bb++) {
                g_bbase[bb * NS + t] = acc;
                acc += g_bh[bb * NS + t];
            }
            int m = (cshr[t] + (TT - 1)) / TT;
            int base = toff_s[t];
            for (int ti = 0; ti < m; ti++)
                for (int tj = ti; tj < m; tj++)
                    g_tiles[base++] = t | (ti << 8) | (tj << 16);
        }
        // pads -> valid row 0 (only the small pad region, up to NS*TT entries)
        if (t < NS * TT) {
            // conservative: re-init whole tail region beyond real slots later via order writes;
            // simplest: init ALL pads here (serial over few entries is fine)
        }
        __syncthreads();
        __threadfence();
        if (t == 0) atomicExch(&g_flag, 1u);   // release
    } else {
        if (t == 0) { while (atomicAdd(&g_flag, 0u) == 0u) { } }   // acquire spin
    }
    __syncthreads();
    __threadfence();

    // phase C0: init pad slots (cheap, every block strides whole array region it owns)
    for (int p = b * 1024 + t; p < MAXP; p += NBLK * 1024) {
        // only pad slots matter; real slots overwritten below (within this kernel,
        // but possibly by OTHER blocks). To avoid racing real slots, write 0 only
        // to the per-subject pad region: slot >= bucket_base + count.
        // Determine subject of this slot:
        // (cheap linear scan over NS=16)
        int s = -1;
        for (int ss = 0; ss < NS; ss++) {
            int lo = g_poff[ss];
            int m  = (g_cnt_s[ss] + (TT - 1)) / TT;
            if (p >= lo && p < lo + m * TT) { s = ss; break; }
        }
        if (s >= 0) {
            if (p >= g_poff[s] + g_cnt_s[s]) g_order[p] = 0;   // pad
        } else {
            g_order[p] = 0;   // beyond all buckets
        }
    }

    // phase C: slot assignment (rank via smem atomics)
    if (t < NS) h[t] = 0;
    __syncthreads();
    if (t < 256) {
        const int i = b * 256 + t;
        const int s = sbj[i];
        const int r = atomicAdd(&h[s], 1);
        g_order[g_bbase[b * NS + s] + r] = i;
    }

    __syncthreads();
    __threadfence();
    if (t == 0) {
        unsigned d = atomicAdd(&g_done3, 1u) + 1u;
        if (d == (unsigned)NBLK) { g_done3 = 0u; g_flag = 0u; }
    }
}

// ---------------- k2: persistent fused Gram over SYMMETRIC 64x64 tiles ----------------
// Gathers rows directly from emb via g_order (no bucket copy). Row bests for
// the tile's 64 rows; for off-diagonal tiles, col bests too via d2 symmetry.
__global__ __launch_bounds__(256) void pair_kernel(const float* __restrict__ emb,
                                                   const int*   __restrict__ labels) {
    __shared__ __align__(16) float As[TK][TT + 4];
    __shared__ __align__(16) float Bs[TK][TT + 4];
    __shared__ int   srcA[TT], srcB[TT];
    __shared__ int   rlab[TT], clab[TT];
    __shared__ float rsq[TT], csq[TT];
    __shared__ unsigned long long colP[8][TT], colN[8][TT];

    const int tid = threadIdx.x;
    const int tx  = tid & 15;    // 16 col-threads x 4 cols
    const int ty  = tid >> 4;    // 16 row-threads x 4 rows
    const int m   = tid >> 2;    // load row 0..63
    const int q   = tid & 3;     // float4 index within chunk
    const int ntiles = g_ntiles;

    for (int t = blockIdx.x; t < ntiles; t += gridDim.x) {
        const int desc = g_tiles[t];
        const int s  = desc & 255;
        const int ti = (desc >> 8) & 255;
        const int tj = (desc >> 16) & 255;
        const int n    = g_cnt_s[s];
        const int base = g_poff[s];
        const int rbase = base + ti * TT;
        const int cbase = base + tj * TT;

        __syncthreads();   // prev tile fully done before smem overwrite
        if (tid < TT) {
            const int ro = g_order[rbase + tid];
            srcA[tid] = ro; rlab[tid] = labels[ro]; rsq[tid] = g_sq[ro];
            const int co = g_order[cbase + tid];
            srcB[tid] = co; clab[tid] = labels[co]; csq[tid] = g_sq[co];
        }
        __syncthreads();

        const float* rowA = emb + (size_t)srcA[m] * ND + q * 4;
        const float* rowB = emb + (size_t)srcB[m] * ND + q * 4;

        float acc[4][4];
#pragma unroll
        for (int a = 0; a < 4; a++)
#pragma unroll
            for (int b = 0; b < 4; b++) acc[a][b] = 0.f;

        // prologue: chunk 0 regs
        float4 va = *(const float4*)(rowA);
        float4 vb = *(const float4*)(rowB);

        for (int kk = 0; kk < ND; kk += TK) {
            As[q * 4 + 0][m] = va.x; As[q * 4 + 1][m] = va.y;
            As[q * 4 + 2][m] = va.z; As[q * 4 + 3][m] = va.w;
            Bs[q * 4 + 0][m] = vb.x; Bs[q * 4 + 1][m] = vb.y;
            Bs[q * 4 + 2][m] = vb.z; Bs[q * 4 + 3][m] = vb.w;
            __syncthreads();
            if (kk + TK < ND) {   // prefetch next chunk (overlaps compute)
                va = *(const float4*)(rowA + kk + TK);
                vb = *(const float4*)(rowB + kk + TK);
            }
#pragma unroll
            for (int k = 0; k < TK; k++) {
                float4 a0 = *(const float4*)&As[k][ty * 4];
                float4 b0 = *(const float4*)&Bs[k][tx * 4];
                float ra[4] = {a0.x, a0.y, a0.z, a0.w};
                float rb[4] = {b0.x, b0.y, b0.z, b0.w};
#pragma unroll
                for (int a = 0; a < 4; a++)
#pragma unroll
                    for (int b = 0; b < 4; b++) acc[a][b] += ra[a] * rb[b];
            }
            __syncthreads();   // compute done before next store
        }

        // ---- row epilogue ----
#pragma unroll
        for (int a = 0; a < 4; a++) {
            const int  rrow   = ty * 4 + a;
            const bool rvalid = (ti * TT + rrow) < n;
            const int   ll = rlab[rrow];
            const int   io = srcA[rrow];
            const float si = rsq [rrow];
            unsigned long long kp = 0ull, kn = ~0ull;
#pragma unroll
            for (int b = 0; b < 4; b++) {
                const int bcol = tx * 4 + b;
                if (rvalid && (tj * TT + bcol) < n) {
                    const float d2v = si + csq[bcol] - 2.f * acc[a][b];
                    const int   jo  = srcB[bcol];
                    if (clab[bcol] == ll) {
                        if (jo != io) {
                            unsigned long long key =
                                ((unsigned long long)ordf(d2v) << 32) |
                                (unsigned long long)(0xFFFFFFFFu - (unsigned)jo);
                            if (key > kp) kp = key;
                        }
                    } else {
                        unsigned long long key =
                            ((unsigned long long)ordf(d2v) << 32) |
                            (unsigned long long)(unsigned)jo;
                        if (key < kn) kn = key;
                    }
                }
            }
#pragma unroll
            for (int o = 1; o < 16; o <<= 1) {
                unsigned long long op = __shfl_xor_sync(0xFFFFFFFFu, kp, o);
                unsigned long long on = __shfl_xor_sync(0xFFFFFFFFu, kn, o);
                if (op > kp) kp = op;
                if (on < kn) kn = on;
            }
            if (tx == 0 && rvalid) {
                if (kp != 0ull)  atomicMax(&g_pos[io], kp);
                if (kn != ~0ull) atomicMin(&g_neg[io], kn);
            }
        }

        // ---- column epilogue (symmetry, off-diagonal only) ----
        if (ti != tj) {
            __syncthreads();
#pragma unroll
            for (int b = 0; b < 4; b++) {
                const int bcol = tx * 4 + b;
                unsigned long long cp = 0ull, cn_ = ~0ull;
                if ((tj * TT + bcol) < n) {
                    const int   llj = clab[bcol];
                    const int   jo  = srcB[bcol];
                    const float sj  = csq [bcol];
#pragma unroll
                    for (int a = 0; a < 4; a++) {
                        const int rrow = ty * 4 + a;
                        if (ti * TT + rrow < n) {
                            const float d2v = rsq[rrow] + sj - 2.f * acc[a][b];
                            const int   io  = srcA[rrow];
                            if (rlab[rrow] == llj) {
                                if (io != jo) {
                                    unsigned long long key =
                                        ((unsigned long long)ordf(d2v) << 32) |
                                        (unsigned long long)(0xFFFFFFFFu - (unsigned)io);
                                    if (key > cp) cp = key;
                                }
                            } else {
                                unsigned long long key =
                                    ((unsigned long long)ordf(d2v) << 32) |
                                    (unsigned long long)(unsigned)io;
                                if (key < cn_) cn_ = key;
                            }
                        }
                    }
                }
                // in-warp reduce across ty parity (lane xor 16), then smem across warps
                unsigned long long op = __shfl_xor_sync(0xFFFFFFFFu, cp,  16);
                unsigned long long on = __shfl_xor_sync(0xFFFFFFFFu, cn_, 16);
                if (op > cp)  cp  = op;
                if (on < cn_) cn_ = on;
                if ((ty & 1) == 0) {
                    colP[ty >> 1][bcol] = cp;
                    colN[ty >> 1][bcol] = cn_;
                }
            }
            __syncthreads();
            if (tid < TT) {
                unsigned long long k = colP[0][tid];
#pragma unroll
                for (int w = 1; w < 8; w++) { unsigned long long v = colP[w][tid]; if (v > k) k = v; }
                if (k != 0ull) atomicMax(&g_pos[srcB[tid]], k);
            } else if (tid < 2 * TT) {
                const int c = tid - TT;
                unsigned long long k = colN[0][c];
#pragma unroll
                for (int w = 1; w < 8; w++) { unsigned long long v = colN[w][c]; if (v < k) k = v; }
                if (k != ~0ull) atomicMin(&g_neg[srcB[c]], k);
            }
        }
    }
}

// ---------------- k3: triplet distances + hierarchical reduce + finalize ----------------
__global__ __launch_bounds__(256) void triplet_kernel(const float* __restrict__ emb,
                                                      float* __restrict__ out) {
    __shared__ float bsum;
    __shared__ int   bcnt;
    if (threadIdx.x == 0) { bsum = 0.f; bcnt = 0; }
    __syncthreads();

    const int wbase = (blockIdx.x * 8 + (threadIdx.x >> 5)) * 2;  // 2 rows per warp
    const int lane  = threadIdx.x & 31;

    float lsum = 0.f;
    int   lcnt = 0;
#pragma unroll
    for (int rr = 0; rr < 2; rr++) {
        const int w = wbase + rr;
        const unsigned long long kp = g_pos[w];
        const unsigned long long kn = g_neg[w];
        if ((kp != 0ull) && (kn != ~0ull)) {
            const int p = (int)(0xFFFFFFFFu - (unsigned)kp);
            const int n = (int)(unsigned)kn;

            const float4 a4 = ((const float4*)(emb + (size_t)w * ND))[lane];
            const float4 p4 = ((const float4*)(emb + (size_t)p * ND))[lane];
            const float4 n4 = ((const float4*)(emb + (size_t)n * ND))[lane];

            float dx, s1, s2;
            dx = a4.x - p4.x + EPSF; s1  = dx * dx;   // torch pairwise_distance eps quirk
            dx = a4.y - p4.y + EPSF; s1 += dx * dx;
            dx = a4.z - p4.z + EPSF; s1 += dx * dx;
            dx = a4.w - p4.w + EPSF; s1 += dx * dx;
            dx = a4.x - n4.x + EPSF; s2  = dx * dx;
            dx = a4.y - n4.y + EPSF; s2 += dx * dx;
            dx = a4.z - n4.z + EPSF; s2 += dx * dx;
            dx = a4.w - n4.w + EPSF; s2 += dx * dx;

#pragma unroll
            for (int o = 16; o > 0; o >>= 1) {
                s1 += __shfl_down_sync(0xFFFFFFFFu, s1, o);
                s2 += __shfl_down_sync(0xFFFFFFFFu, s2, o);
            }
            if (lane == 0) {
                lsum += fmaxf(sqrtf(s1) - sqrtf(s2) + MARGIN, 0.f);
                lcnt += 1;
            }
        }
    }
    if (lane == 0 && lcnt > 0) {
        atomicAdd(&bsum, lsum);
        atomicAdd(&bcnt, lcnt);
    }
    __syncthreads();
    if (threadIdx.x == 0) {
        if (bcnt > 0) {
            atomicAdd(&g_sum, bsum);
            atomicAdd(&g_cnt, bcnt);
        }
        __threadfence();
        unsigned done = atomicAdd(&g_done2, 1u) + 1u;
        if (done == gridDim.x) {
            float sm = atomicAdd(&g_sum, 0.f);
            int   c  = atomicAdd(&g_cnt, 0);
            out[0] = (c > 0) ? sm / (float)c : 0.f;
            g_done2 = 0u;   // reset for next replay
        }
    }
}

// ---------------- launch ----------------
extern "C" void kernel_launch(void* const* d_in, const int* in_sizes, int n_in,
                              void* d_out, int out_size) {
    const float* emb    = (const float*)d_in[0];
    const int*   labels = (const int*)d_in[1];
    const int*   sbj    = (const int*)d_in[2];
    float*       out    = (float*)d_out;

    prep_kernel   <<<NBLK, 1024>>>(emb, sbj);
    pair_kernel   <<<PAIR_GRID, 256>>>(emb, labels);
    triplet_kernel<<<NB / 16, 256>>>(emb, out);
}